// round 14
// baseline (speedup 1.0000x reference)
#include <cuda_runtime.h>
#include <cuda_fp16.h>
#include <cstdint>

#define DIN   256
#define DOUT  128
#define NMAX  100000
#define EMAX  3200000

// ---------------- scratch (static device globals — allocation-free) ----------
__device__ __align__(16) __half g_h16[(size_t)NMAX * DOUT];  // 25.6 MB, fp16 h (UNSCALED)
__device__ int   g_outdeg[NMAX];
__device__ int   g_indeg [NMAX];
__device__ float g_scout [NMAX];               // out_deg^-1/2
__device__ float g_scin  [NMAX];               // in_deg^-1/2
__device__ int   g_off   [NMAX + 1];           // CSR offsets (by dst)
__device__ int   g_cursor[NMAX];               // placement cursors
__device__ int   g_bsum  [1024];               // block sums for scan
__device__ int   g_csrc  [EMAX];               // CSR payload: src node per slot
__device__ __align__(16) __half g_w16[DOUT * DIN];  // W^T as fp16 [n][k], 64 KB

// ---------------------------------------------------------------- both histograms (one pass)
__global__ void k_count(const int* __restrict__ src, const int* __restrict__ dst, int nE) {
    int i = blockIdx.x * blockDim.x + threadIdx.x;
    int base = i * 4;
    if (base + 3 < nE) {
        int4 s = *(const int4*)&src[base];
        int4 d = *(const int4*)&dst[base];
        atomicAdd(&g_outdeg[s.x], 1);
        atomicAdd(&g_outdeg[s.y], 1);
        atomicAdd(&g_outdeg[s.z], 1);
        atomicAdd(&g_outdeg[s.w], 1);
        atomicAdd(&g_indeg[d.x], 1);
        atomicAdd(&g_indeg[d.y], 1);
        atomicAdd(&g_indeg[d.z], 1);
        atomicAdd(&g_indeg[d.w], 1);
    } else {
        for (int e = base; e < nE; e++) {
            atomicAdd(&g_outdeg[src[e]], 1);
            atomicAdd(&g_indeg [dst[e]], 1);
        }
    }
}

// ---------------------------------------------------------------- prep B (fp16)
__global__ void k_prepB(const float* __restrict__ w) {
    int i = blockIdx.x * blockDim.x + threadIdx.x;
    if (i >= DIN * DOUT) return;
    int n = i / DIN, k = i % DIN;
    g_w16[i] = __float2half_rn(w[(size_t)k * DOUT + n]);
}

// ---------------------------------------------------------------- scan stage 1
__global__ __launch_bounds__(256) void k_scan1(int n) {
    __shared__ int sh[256];
    int i = blockIdx.x * 256 + threadIdx.x;
    int v = (i < n) ? g_indeg[i] : 0;
    sh[threadIdx.x] = v;
    __syncthreads();
    #pragma unroll
    for (int off = 1; off < 256; off <<= 1) {
        int t = (threadIdx.x >= off) ? sh[threadIdx.x - off] : 0;
        __syncthreads();
        sh[threadIdx.x] += t;
        __syncthreads();
    }
    if (i < n) g_off[i] = sh[threadIdx.x] - v;
    if (threadIdx.x == 255) g_bsum[blockIdx.x] = sh[255];
}

// ---------------------------------------------------------------- scan stage 2
__global__ __launch_bounds__(1024) void k_scan2(int nb) {
    __shared__ int sh[1024];
    int t = threadIdx.x;
    int v = (t < nb) ? g_bsum[t] : 0;
    sh[t] = v;
    __syncthreads();
    #pragma unroll
    for (int off = 1; off < 1024; off <<= 1) {
        int x = (t >= off) ? sh[t - off] : 0;
        __syncthreads();
        sh[t] += x;
        __syncthreads();
    }
    if (t < nb) g_bsum[t] = sh[t] - v;
}

// ---------------------------------------------------------------- scan stage 3 (+ scin + scout)
__global__ void k_scan3(int n, int nE) {
    int i = blockIdx.x * blockDim.x + threadIdx.x;
    if (i < n) {
        int o = g_off[i] + g_bsum[blockIdx.x];
        g_off[i] = o;
        g_cursor[i] = o;
        g_scin [i] = rsqrtf(fmaxf((float)g_indeg [i], 1.0f));
        g_scout[i] = rsqrtf(fmaxf((float)g_outdeg[i], 1.0f));
    }
    if (i == 0) g_off[n] = nE;
}

// ---------------------------------------------------------------- CSR build (placement only)
__global__ void k_build(const int* __restrict__ src, const int* __restrict__ dst, int nE) {
    int i = blockIdx.x * blockDim.x + threadIdx.x;
    int base = i * 4;
    if (base + 3 < nE) {
        int4 s = *(const int4*)&src[base];
        int4 d = *(const int4*)&dst[base];
        int p0 = atomicAdd(&g_cursor[d.x], 1);
        int p1 = atomicAdd(&g_cursor[d.y], 1);
        int p2 = atomicAdd(&g_cursor[d.z], 1);
        int p3 = atomicAdd(&g_cursor[d.w], 1);
        g_csrc[p0] = s.x;
        g_csrc[p1] = s.y;
        g_csrc[p2] = s.z;
        g_csrc[p3] = s.w;
    } else {
        for (int e = base; e < nE; e++) {
            int p = atomicAdd(&g_cursor[dst[e]], 1);
            g_csrc[p] = src[e];
        }
    }
}

// ---------------------------------------------------------------- GEMM (fp16 HMMA + ldmatrix)
// h = feat @ W (unscaled — scout applied in gather). 2 CTAs/SM. Zero deps.
#define BK      64
#define PITCH_A 72
#define PITCH_B 264

__device__ __forceinline__ void mma16816(float* d, const uint32_t* a, const uint32_t* b) {
    asm volatile(
        "mma.sync.aligned.m16n8k16.row.col.f32.f16.f16.f32 "
        "{%0,%1,%2,%3}, {%4,%5,%6,%7}, {%8,%9}, {%0,%1,%2,%3};"
        : "+f"(d[0]), "+f"(d[1]), "+f"(d[2]), "+f"(d[3])
        : "r"(a[0]), "r"(a[1]), "r"(a[2]), "r"(a[3]), "r"(b[0]), "r"(b[1]));
}

#define LDSM_X4(r0, r1, r2, r3, addr)                                           \
    asm volatile("ldmatrix.sync.aligned.m8n8.x4.shared.b16 {%0,%1,%2,%3}, [%4];" \
                 : "=r"(r0), "=r"(r1), "=r"(r2), "=r"(r3) : "r"(addr))

#define GEMM_SMEM ((128 * PITCH_B + 128 * PITCH_A) * 2)  /* 86,016 B */

__global__ __launch_bounds__(256, 2) void k_gemm_mma(const float* __restrict__ feat, int M) {
    extern __shared__ __half sm[];
    __half* Bs = sm;                       // [128 n][PITCH_B] full K fp16
    __half* As = Bs + 128 * PITCH_B;       // [128 r][PITCH_A] one chunk

    const int tid  = threadIdx.x;
    const int wid  = tid >> 5, lane = tid & 31;
    const int g    = lane >> 2, t = lane & 3;
    const int wm   = wid & 3, wn = wid >> 2;     // warp grid 4(M) x 2(N)
    const int brow = blockIdx.x * 128;

    // ---- B resident copy
    #pragma unroll
    for (int i = 0; i < 16; i++) {
        int idx = tid + i * 256;
        int n   = idx >> 5;
        int j   = (idx & 31) * 8;
        *(uint4*)&Bs[n * PITCH_B + j] = *(const uint4*)&g_w16[n * DIN + j];
    }

    float acc[2][8][4];
    #pragma unroll
    for (int m = 0; m < 2; m++)
        #pragma unroll
        for (int s = 0; s < 8; s++)
            #pragma unroll
            for (int q = 0; q < 4; q++) acc[m][s][q] = 0.f;

    // ---- ldmatrix per-lane base addresses
    const int la = lane & 7;
    const int lb = (lane >> 3) & 1;
    const int lc = (lane >> 4) & 1;
    uint32_t a_base = (uint32_t)__cvta_generic_to_shared(As)
                    + (uint32_t)((wm * 32 + la + lb * 8) * PITCH_A) * 2 + (uint32_t)lc * 16;
    uint32_t b_base = (uint32_t)__cvta_generic_to_shared(Bs)
                    + (uint32_t)((wn * 64 + lc * 8 + la) * PITCH_B) * 2 + (uint32_t)lb * 16;

    __syncthreads();   // B ready

    for (int c = 0; c < 4; c++) {
        // ---- load + convert A chunk
        #pragma unroll
        for (int i = 0; i < 8; i++) {
            int idx = tid + i * 256;
            int r = idx >> 4, c4 = (idx & 15) * 4;
            int gr = brow + r;
            float4 x = (gr < M) ? *(const float4*)&feat[(size_t)gr * DIN + c * BK + c4]
                                : make_float4(0.f, 0.f, 0.f, 0.f);
            __half2 h0 = __floats2half2_rn(x.x, x.y);
            __half2 h1 = __floats2half2_rn(x.z, x.w);
            *(uint2*)&As[r * PITCH_A + c4] = make_uint2(*(uint32_t*)&h0, *(uint32_t*)&h1);
        }
        __syncthreads();

        const int kb = c * BK;
        #pragma unroll
        for (int ks = 0; ks < 4; ks++) {
            const int kk = ks * 16;
            uint32_t a[2][4];
            #pragma unroll
            for (int m = 0; m < 2; m++) {
                uint32_t ad = a_base + (uint32_t)(m * 16 * PITCH_A) * 2 + (uint32_t)kk * 2;
                LDSM_X4(a[m][0], a[m][1], a[m][2], a[m][3], ad);
            }
            #pragma unroll
            for (int j = 0; j < 4; j++) {
                uint32_t q0, q1, q2, q3;
                uint32_t bd = b_base + (uint32_t)(j * 16 * PITCH_B) * 2 + (uint32_t)(kb + kk) * 2;
                LDSM_X4(q0, q1, q2, q3, bd);
                uint32_t b0[2] = {q0, q1};
                uint32_t b1[2] = {q2, q3};
                #pragma unroll
                for (int m = 0; m < 2; m++) {
                    mma16816(acc[m][2 * j],     a[m], b0);
                    mma16816(acc[m][2 * j + 1], a[m], b1);
                }
            }
        }
        __syncthreads();
    }

    // ---- epilogue: store fp16 (unscaled)
    #pragma unroll
    for (int m = 0; m < 2; m++) {
        int r0 = brow + wm * 32 + m * 16 + g;
        int r1 = r0 + 8;
        #pragma unroll
        for (int s = 0; s < 8; s++) {
            int cb = wn * 64 + s * 8 + 2 * t;
            if (r0 < M) *(__half2*)&g_h16[(size_t)r0 * DOUT + cb] =
                __floats2half2_rn(acc[m][s][0], acc[m][s][1]);
            if (r1 < M) *(__half2*)&g_h16[(size_t)r1 * DOUT + cb] =
                __floats2half2_rn(acc[m][s][2], acc[m][s][3]);
        }
    }
}

// ---------------------------------------------------------------- gather-agg
// Full warp per dst node; lane owns 4 consecutive cols (uint2 of fp16).
// acc += scout[src] * h[src]; out = acc*scin + bias.
__global__ __launch_bounds__(256) void k_gather(float* __restrict__ out,
                                                const float* __restrict__ bias,
                                                int M) {
    long gid  = (long)blockIdx.x * blockDim.x + threadIdx.x;
    int  node = (int)(gid >> 5);
    int  lane = (int)(gid & 31);
    if (node >= M) return;

    int beg = g_off[node];
    int end = g_off[node + 1];

    const uint2* hp = (const uint2*)g_h16;   // row = 32 uint2 (128 halves)
    float acc[4];
    #pragma unroll
    for (int j = 0; j < 4; j++) acc[j] = 0.f;

    int e = beg;
    for (; e + 4 <= end; e += 4) {
        int s0 = __ldcs(&g_csrc[e]),   s1 = __ldcs(&g_csrc[e+1]);
        int s2 = __ldcs(&g_csrc[e+2]), s3 = __ldcs(&g_csrc[e+3]);
        float w0 = __ldg(&g_scout[s0]), w1 = __ldg(&g_scout[s1]);
        float w2 = __ldg(&g_scout[s2]), w3 = __ldg(&g_scout[s3]);
        uint2 q0 = __ldg(hp + (size_t)s0 * 32 + lane);
        uint2 q1 = __ldg(hp + (size_t)s1 * 32 + lane);
        uint2 q2 = __ldg(hp + (size_t)s2 * 32 + lane);
        uint2 q3 = __ldg(hp + (size_t)s3 * 32 + lane);
        #pragma unroll
        for (int p = 0; p < 2; p++) {
            uint32_t u0 = (&q0.x)[p], u1 = (&q1.x)[p], u2 = (&q2.x)[p], u3 = (&q3.x)[p];
            float2 f0 = __half22float2(*(__half2*)&u0);
            float2 f1 = __half22float2(*(__half2*)&u1);
            float2 f2 = __half22float2(*(__half2*)&u2);
            float2 f3 = __half22float2(*(__half2*)&u3);
            acc[2*p]   = fmaf(f0.x, w0, fmaf(f1.x, w1, fmaf(f2.x, w2, fmaf(f3.x, w3, acc[2*p]))));
            acc[2*p+1] = fmaf(f0.y, w0, fmaf(f1.y, w1, fmaf(f2.y, w2, fmaf(f3.y, w3, acc[2*p+1]))));
        }
    }
    for (; e < end; e++) {
        int s = __ldcs(&g_csrc[e]);
        float w = __ldg(&g_scout[s]);
        uint2 q = __ldg(hp + (size_t)s * 32 + lane);
        #pragma unroll
        for (int p = 0; p < 2; p++) {
            uint32_t u = (&q.x)[p];
            float2 f = __half22float2(*(__half2*)&u);
            acc[2*p]   = fmaf(f.x, w, acc[2*p]);
            acc[2*p+1] = fmaf(f.y, w, acc[2*p+1]);
        }
    }

    float sc = g_scin[node];
    float4 b = *(const float4*)&bias[lane * 4];
    float4 r = make_float4(fmaf(acc[0], sc, b.x), fmaf(acc[1], sc, b.y),
                           fmaf(acc[2], sc, b.z), fmaf(acc[3], sc, b.w));
    __stcs((float4*)&out[(size_t)node * DOUT + lane * 4], r);
}

// ---------------------------------------------------------------- launch
extern "C" void kernel_launch(void* const* d_in, const int* in_sizes, int n_in,
                              void* d_out, int out_size) {
    const float* feat   = (const float*)d_in[0];
    const float* weight = (const float*)d_in[1];
    const float* bias   = (const float*)d_in[2];
    const int*   src    = (const int*)  d_in[3];
    const int*   dst    = (const int*)  d_in[4];

    int M  = in_sizes[0] / DIN;   // 100000
    int nE = in_sizes[3];         // 3200000
    int nb = (M + 255) / 256;
    int nE4 = (nE + 3) / 4;

    static cudaStream_t s2;
    static cudaEvent_t evFork, evJoin;
    static void *pIndeg, *pOutdeg;
    static int inited = 0;
    if (!inited) {
        cudaFuncSetAttribute(k_gemm_mma, cudaFuncAttributeMaxDynamicSharedMemorySize, GEMM_SMEM);
        cudaStreamCreateWithFlags(&s2, cudaStreamNonBlocking);
        cudaEventCreateWithFlags(&evFork, cudaEventDisableTiming);
        cudaEventCreateWithFlags(&evJoin, cudaEventDisableTiming);
        cudaGetSymbolAddress(&pIndeg,  g_indeg);
        cudaGetSymbolAddress(&pOutdeg, g_outdeg);
        inited = 1;
    }

    // ---- fork immediately: s2 = prepB + gemm (zero dependencies, DRAM/tensor-bound)
    cudaEventRecord(evFork, 0);
    cudaStreamWaitEvent(s2, evFork, 0);
    k_prepB   <<<(DIN * DOUT + 255) / 256, 256, 0, s2>>>(weight);
    k_gemm_mma<<<(M + 127) / 128, 256, GEMM_SMEM, s2>>>(feat, M);
    cudaEventRecord(evJoin, s2);

    // ---- main: CSR chain (LTS-bound)
    cudaMemsetAsync(pIndeg,  0, (size_t)M * sizeof(int), 0);
    cudaMemsetAsync(pOutdeg, 0, (size_t)M * sizeof(int), 0);
    k_count<<<(nE4 + 255) / 256, 256>>>(src, dst, nE);
    k_scan1<<<nb, 256>>>(M);
    k_scan2<<<1, 1024>>>(nb);
    k_scan3<<<nb, 256>>>(M, nE);
    k_build<<<(nE4 + 255) / 256, 256>>>(src, dst, nE);

    // ---- join, then gather
    cudaStreamWaitEvent(0, evJoin, 0);
    long gather_threads = (long)M * 32;
    k_gather<<<(unsigned)((gather_threads + 255) / 256), 256>>>((float*)d_out, bias, M);
}

// round 15
// speedup vs baseline: 1.0491x; 1.0491x over previous
#include <cuda_runtime.h>
#include <cuda_fp16.h>
#include <cstdint>

#define DIN   256
#define DOUT  128
#define NMAX  100000
#define EMAX  3200000

// ---------------- scratch (static device globals — allocation-free) ----------
__device__ __align__(16) __half g_h16[(size_t)NMAX * DOUT];  // 25.6 MB, fp16 h (scout-scaled)
__device__ int   g_outdeg[NMAX];
__device__ int   g_indeg [NMAX];
__device__ float g_scout [NMAX];               // out_deg^-1/2
__device__ float g_scin  [NMAX];               // in_deg^-1/2
__device__ int   g_off   [NMAX + 1];           // CSR offsets (by dst)
__device__ int   g_cursor[NMAX];               // placement cursors
__device__ int   g_bsum  [1024];               // block sums for scan
__device__ int   g_csrc  [EMAX];               // CSR payload: src node per slot
__device__ __align__(16) __half g_w16[DOUT * DIN];  // W^T as fp16 [n][k], 64 KB

// ---------------------------------------------------------------- dst histogram (8/thread)
__global__ void k_count_dst(const int* __restrict__ dst, int nE) {
    int i = blockIdx.x * blockDim.x + threadIdx.x;
    int base = i * 8;
    if (base + 7 < nE) {
        int4 d0 = *(const int4*)&dst[base];
        int4 d1 = *(const int4*)&dst[base + 4];
        atomicAdd(&g_indeg[d0.x], 1);
        atomicAdd(&g_indeg[d0.y], 1);
        atomicAdd(&g_indeg[d0.z], 1);
        atomicAdd(&g_indeg[d0.w], 1);
        atomicAdd(&g_indeg[d1.x], 1);
        atomicAdd(&g_indeg[d1.y], 1);
        atomicAdd(&g_indeg[d1.z], 1);
        atomicAdd(&g_indeg[d1.w], 1);
    } else {
        for (int e = base; e < nE; e++) atomicAdd(&g_indeg[dst[e]], 1);
    }
}

// ---------------------------------------------------------------- src histogram (8/thread)
__global__ void k_count_src(const int* __restrict__ src, int nE) {
    int i = blockIdx.x * blockDim.x + threadIdx.x;
    int base = i * 8;
    if (base + 7 < nE) {
        int4 s0 = *(const int4*)&src[base];
        int4 s1 = *(const int4*)&src[base + 4];
        atomicAdd(&g_outdeg[s0.x], 1);
        atomicAdd(&g_outdeg[s0.y], 1);
        atomicAdd(&g_outdeg[s0.z], 1);
        atomicAdd(&g_outdeg[s0.w], 1);
        atomicAdd(&g_outdeg[s1.x], 1);
        atomicAdd(&g_outdeg[s1.y], 1);
        atomicAdd(&g_outdeg[s1.z], 1);
        atomicAdd(&g_outdeg[s1.w], 1);
    } else {
        for (int e = base; e < nE; e++) atomicAdd(&g_outdeg[src[e]], 1);
    }
}

// ---------------------------------------------------------------- prep B (fp16)
__global__ void k_prepB(const float* __restrict__ w) {
    int i = blockIdx.x * blockDim.x + threadIdx.x;
    if (i >= DIN * DOUT) return;
    int n = i / DIN, k = i % DIN;
    g_w16[i] = __float2half_rn(w[(size_t)k * DOUT + n]);
}

// ---------------------------------------------------------------- scan stage 1
__global__ __launch_bounds__(256) void k_scan1(int n) {
    __shared__ int sh[256];
    int i = blockIdx.x * 256 + threadIdx.x;
    int v = (i < n) ? g_indeg[i] : 0;
    sh[threadIdx.x] = v;
    __syncthreads();
    #pragma unroll
    for (int off = 1; off < 256; off <<= 1) {
        int t = (threadIdx.x >= off) ? sh[threadIdx.x - off] : 0;
        __syncthreads();
        sh[threadIdx.x] += t;
        __syncthreads();
    }
    if (i < n) g_off[i] = sh[threadIdx.x] - v;
    if (threadIdx.x == 255) g_bsum[blockIdx.x] = sh[255];
}

// ---------------------------------------------------------------- scan stage 2
__global__ __launch_bounds__(1024) void k_scan2(int nb) {
    __shared__ int sh[1024];
    int t = threadIdx.x;
    int v = (t < nb) ? g_bsum[t] : 0;
    sh[t] = v;
    __syncthreads();
    #pragma unroll
    for (int off = 1; off < 1024; off <<= 1) {
        int x = (t >= off) ? sh[t - off] : 0;
        __syncthreads();
        sh[t] += x;
        __syncthreads();
    }
    if (t < nb) g_bsum[t] = sh[t] - v;
}

// ---------------------------------------------------------------- scan stage 3 (+ scin)
__global__ void k_scan3(int n, int nE) {
    int i = blockIdx.x * blockDim.x + threadIdx.x;
    if (i < n) {
        int o = g_off[i] + g_bsum[blockIdx.x];
        g_off[i] = o;
        g_cursor[i] = o;
        g_scin[i] = rsqrtf(fmaxf((float)g_indeg[i], 1.0f));
    }
    if (i == 0) g_off[n] = nE;
}

// ---------------------------------------------------------------- CSR build (8 edges/thread)
__global__ void k_build(const int* __restrict__ src, const int* __restrict__ dst, int nE) {
    int i = blockIdx.x * blockDim.x + threadIdx.x;
    int base = i * 8;
    if (base + 7 < nE) {
        int4 s0 = *(const int4*)&src[base];
        int4 s1 = *(const int4*)&src[base + 4];
        int4 d0 = *(const int4*)&dst[base];
        int4 d1 = *(const int4*)&dst[base + 4];
        int p0 = atomicAdd(&g_cursor[d0.x], 1);
        int p1 = atomicAdd(&g_cursor[d0.y], 1);
        int p2 = atomicAdd(&g_cursor[d0.z], 1);
        int p3 = atomicAdd(&g_cursor[d0.w], 1);
        int p4 = atomicAdd(&g_cursor[d1.x], 1);
        int p5 = atomicAdd(&g_cursor[d1.y], 1);
        int p6 = atomicAdd(&g_cursor[d1.z], 1);
        int p7 = atomicAdd(&g_cursor[d1.w], 1);
        g_csrc[p0] = s0.x;
        g_csrc[p1] = s0.y;
        g_csrc[p2] = s0.z;
        g_csrc[p3] = s0.w;
        g_csrc[p4] = s1.x;
        g_csrc[p5] = s1.y;
        g_csrc[p6] = s1.z;
        g_csrc[p7] = s1.w;
    } else {
        for (int e = base; e < nE; e++) {
            int p = atomicAdd(&g_cursor[dst[e]], 1);
            g_csrc[p] = src[e];
        }
    }
}

// ---------------------------------------------------------------- scout
__global__ void k_scout(int n) {
    int i = blockIdx.x * blockDim.x + threadIdx.x;
    if (i < n) g_scout[i] = rsqrtf(fmaxf((float)g_outdeg[i], 1.0f));
}

// ---------------------------------------------------------------- GEMM (fp16 HMMA + ldmatrix)
// h = scout * (feat @ W), fp16 out. B (full K) resident in smem. 2 CTAs/SM.
#define BK      64
#define PITCH_A 72
#define PITCH_B 264

__device__ __forceinline__ void mma16816(float* d, const uint32_t* a, const uint32_t* b) {
    asm volatile(
        "mma.sync.aligned.m16n8k16.row.col.f32.f16.f16.f32 "
        "{%0,%1,%2,%3}, {%4,%5,%6,%7}, {%8,%9}, {%0,%1,%2,%3};"
        : "+f"(d[0]), "+f"(d[1]), "+f"(d[2]), "+f"(d[3])
        : "r"(a[0]), "r"(a[1]), "r"(a[2]), "r"(a[3]), "r"(b[0]), "r"(b[1]));
}

#define LDSM_X4(r0, r1, r2, r3, addr)                                           \
    asm volatile("ldmatrix.sync.aligned.m8n8.x4.shared.b16 {%0,%1,%2,%3}, [%4];" \
                 : "=r"(r0), "=r"(r1), "=r"(r2), "=r"(r3) : "r"(addr))

#define GEMM_SMEM ((128 * PITCH_B + 128 * PITCH_A) * 2)  /* 86,016 B */

__global__ __launch_bounds__(256, 2) void k_gemm_mma(const float* __restrict__ feat, int M) {
    extern __shared__ __half sm[];
    __half* Bs = sm;                       // [128 n][PITCH_B] full K fp16
    __half* As = Bs + 128 * PITCH_B;       // [128 r][PITCH_A] one chunk

    const int tid  = threadIdx.x;
    const int wid  = tid >> 5, lane = tid & 31;
    const int g    = lane >> 2, t = lane & 3;
    const int wm   = wid & 3, wn = wid >> 2;     // warp grid 4(M) x 2(N)
    const int brow = blockIdx.x * 128;

    // ---- B resident copy
    #pragma unroll
    for (int i = 0; i < 16; i++) {
        int idx = tid + i * 256;
        int n   = idx >> 5;
        int j   = (idx & 31) * 8;
        *(uint4*)&Bs[n * PITCH_B + j] = *(const uint4*)&g_w16[n * DIN + j];
    }

    float acc[2][8][4];
    #pragma unroll
    for (int m = 0; m < 2; m++)
        #pragma unroll
        for (int s = 0; s < 8; s++)
            #pragma unroll
            for (int q = 0; q < 4; q++) acc[m][s][q] = 0.f;

    // ---- ldmatrix per-lane base addresses
    const int la = lane & 7;
    const int lb = (lane >> 3) & 1;
    const int lc = (lane >> 4) & 1;
    uint32_t a_base = (uint32_t)__cvta_generic_to_shared(As)
                    + (uint32_t)((wm * 32 + la + lb * 8) * PITCH_A) * 2 + (uint32_t)lc * 16;
    uint32_t b_base = (uint32_t)__cvta_generic_to_shared(Bs)
                    + (uint32_t)((wn * 64 + lc * 8 + la) * PITCH_B) * 2 + (uint32_t)lb * 16;

    __syncthreads();   // B ready

    for (int c = 0; c < 4; c++) {
        // ---- load + convert A chunk
        #pragma unroll
        for (int i = 0; i < 8; i++) {
            int idx = tid + i * 256;
            int r = idx >> 4, c4 = (idx & 15) * 4;
            int gr = brow + r;
            float4 x = (gr < M) ? *(const float4*)&feat[(size_t)gr * DIN + c * BK + c4]
                                : make_float4(0.f, 0.f, 0.f, 0.f);
            __half2 h0 = __floats2half2_rn(x.x, x.y);
            __half2 h1 = __floats2half2_rn(x.z, x.w);
            *(uint2*)&As[r * PITCH_A + c4] = make_uint2(*(uint32_t*)&h0, *(uint32_t*)&h1);
        }
        __syncthreads();

        const int kb = c * BK;
        #pragma unroll
        for (int ks = 0; ks < 4; ks++) {
            const int kk = ks * 16;
            uint32_t a[2][4];
            #pragma unroll
            for (int m = 0; m < 2; m++) {
                uint32_t ad = a_base + (uint32_t)(m * 16 * PITCH_A) * 2 + (uint32_t)kk * 2;
                LDSM_X4(a[m][0], a[m][1], a[m][2], a[m][3], ad);
            }
            #pragma unroll
            for (int j = 0; j < 4; j++) {
                uint32_t q0, q1, q2, q3;
                uint32_t bd = b_base + (uint32_t)(j * 16 * PITCH_B) * 2 + (uint32_t)(kb + kk) * 2;
                LDSM_X4(q0, q1, q2, q3, bd);
                uint32_t b0[2] = {q0, q1};
                uint32_t b1[2] = {q2, q3};
                #pragma unroll
                for (int m = 0; m < 2; m++) {
                    mma16816(acc[m][2 * j],     a[m], b0);
                    mma16816(acc[m][2 * j + 1], a[m], b1);
                }
            }
        }
        __syncthreads();
    }

    // ---- epilogue: scale by scout[row], store fp16
    #pragma unroll
    for (int m = 0; m < 2; m++) {
        int r0 = brow + wm * 32 + m * 16 + g;
        int r1 = r0 + 8;
        float so0 = (r0 < M) ? __ldg(&g_scout[r0]) : 0.f;
        float so1 = (r1 < M) ? __ldg(&g_scout[r1]) : 0.f;
        #pragma unroll
        for (int s = 0; s < 8; s++) {
            int cb = wn * 64 + s * 8 + 2 * t;
            if (r0 < M) *(__half2*)&g_h16[(size_t)r0 * DOUT + cb] =
                __floats2half2_rn(acc[m][s][0] * so0, acc[m][s][1] * so0);
            if (r1 < M) *(__half2*)&g_h16[(size_t)r1 * DOUT + cb] =
                __floats2half2_rn(acc[m][s][2] * so1, acc[m][s][3] * so1);
        }
    }
}

// ---------------------------------------------------------------- gather-agg
// Full warp per dst node; lane owns 4 consecutive cols (uint2 of fp16).
// No intra-warp divergence. h already scout-scaled -> pure sum.
__global__ __launch_bounds__(256) void k_gather(float* __restrict__ out,
                                                const float* __restrict__ bias,
                                                int M) {
    long gid  = (long)blockIdx.x * blockDim.x + threadIdx.x;
    int  node = (int)(gid >> 5);
    int  lane = (int)(gid & 31);
    if (node >= M) return;

    int beg = g_off[node];
    int end = g_off[node + 1];

    const uint2* hp = (const uint2*)g_h16;   // row = 32 uint2 (128 halves)
    float acc[4];
    #pragma unroll
    for (int j = 0; j < 4; j++) acc[j] = 0.f;

    int e = beg;
    for (; e + 4 <= end; e += 4) {
        int s0 = __ldcs(&g_csrc[e]),   s1 = __ldcs(&g_csrc[e+1]);
        int s2 = __ldcs(&g_csrc[e+2]), s3 = __ldcs(&g_csrc[e+3]);
        uint2 q0 = __ldg(hp + (size_t)s0 * 32 + lane);
        uint2 q1 = __ldg(hp + (size_t)s1 * 32 + lane);
        uint2 q2 = __ldg(hp + (size_t)s2 * 32 + lane);
        uint2 q3 = __ldg(hp + (size_t)s3 * 32 + lane);
        #pragma unroll
        for (int p = 0; p < 2; p++) {
            uint32_t u0 = (&q0.x)[p], u1 = (&q1.x)[p], u2 = (&q2.x)[p], u3 = (&q3.x)[p];
            float2 f0 = __half22float2(*(__half2*)&u0);
            float2 f1 = __half22float2(*(__half2*)&u1);
            float2 f2 = __half22float2(*(__half2*)&u2);
            float2 f3 = __half22float2(*(__half2*)&u3);
            acc[2*p]   += (f0.x + f1.x) + (f2.x + f3.x);
            acc[2*p+1] += (f0.y + f1.y) + (f2.y + f3.y);
        }
    }
    for (; e < end; e++) {
        int s = __ldcs(&g_csrc[e]);
        uint2 q = __ldg(hp + (size_t)s * 32 + lane);
        #pragma unroll
        for (int p = 0; p < 2; p++) {
            uint32_t u = (&q.x)[p];
            float2 f = __half22float2(*(__half2*)&u);
            acc[2*p]   += f.x;
            acc[2*p+1] += f.y;
        }
    }

    float sc = g_scin[node];
    float4 b = *(const float4*)&bias[lane * 4];
    float4 r = make_float4(fmaf(acc[0], sc, b.x), fmaf(acc[1], sc, b.y),
                           fmaf(acc[2], sc, b.z), fmaf(acc[3], sc, b.w));
    __stcs((float4*)&out[(size_t)node * DOUT + lane * 4], r);
}

// ---------------------------------------------------------------- launch
extern "C" void kernel_launch(void* const* d_in, const int* in_sizes, int n_in,
                              void* d_out, int out_size) {
    const float* feat   = (const float*)d_in[0];
    const float* weight = (const float*)d_in[1];
    const float* bias   = (const float*)d_in[2];
    const int*   src    = (const int*)  d_in[3];
    const int*   dst    = (const int*)  d_in[4];

    int M  = in_sizes[0] / DIN;   // 100000
    int nE = in_sizes[3];         // 3200000
    int nb = (M + 255) / 256;
    int nE8 = (nE + 7) / 8;

    static cudaStream_t s2;
    static cudaEvent_t evFork, evJoin;
    static void *pIndeg, *pOutdeg;
    static int inited = 0;
    if (!inited) {
        cudaFuncSetAttribute(k_gemm_mma, cudaFuncAttributeMaxDynamicSharedMemorySize, GEMM_SMEM);
        cudaStreamCreateWithFlags(&s2, cudaStreamNonBlocking);
        cudaEventCreateWithFlags(&evFork, cudaEventDisableTiming);
        cudaEventCreateWithFlags(&evJoin, cudaEventDisableTiming);
        cudaGetSymbolAddress(&pIndeg,  g_indeg);
        cudaGetSymbolAddress(&pOutdeg, g_outdeg);
        inited = 1;
    }

    // ---- shared prologue: zero both degree arrays via memset, then fork
    cudaMemsetAsync(pIndeg,  0, (size_t)M * sizeof(int), 0);
    cudaMemsetAsync(pOutdeg, 0, (size_t)M * sizeof(int), 0);
    cudaEventRecord(evFork, 0);
    cudaStreamWaitEvent(s2, evFork, 0);

    // ---- s2: src-scale + gemm branch (scout before gemm epilogue)
    k_count_src<<<(nE8 + 255) / 256, 256, 0, s2>>>(src, nE);
    k_scout    <<<(M + 255) / 256, 256, 0, s2>>>(M);
    k_prepB    <<<(DIN * DOUT + 255) / 256, 256, 0, s2>>>(weight);
    k_gemm_mma <<<(M + 127) / 128, 256, GEMM_SMEM, s2>>>(feat, M);
    cudaEventRecord(evJoin, s2);

    // ---- main: CSR branch
    k_count_dst<<<(nE8 + 255) / 256, 256>>>(dst, nE);
    k_scan1<<<nb, 256>>>(M);
    k_scan2<<<1, 1024>>>(nb);
    k_scan3<<<nb, 256>>>(M, nE);
    k_build<<<(nE8 + 255) / 256, 256>>>(src, dst, nE);

    // ---- join, then gather
    cudaStreamWaitEvent(0, evJoin, 0);
    long gather_threads = (long)M * 32;
    k_gather<<<(unsigned)((gather_threads + 255) / 256), 256>>>((float*)d_out, bias, M);
}

// round 16
// speedup vs baseline: 1.0844x; 1.0336x over previous
#include <cuda_runtime.h>
#include <cuda_fp16.h>
#include <cstdint>

#define DIN   256
#define DOUT  128
#define NMAX  100000
#define EMAX  3200000

// ---------------- scratch (static device globals — allocation-free) ----------
__device__ __align__(16) __half g_h16[(size_t)NMAX * DOUT];  // 25.6 MB, fp16 h (scout-scaled)
__device__ int   g_outdeg[NMAX];
__device__ int   g_indeg [NMAX];
__device__ float g_scout [NMAX];               // out_deg^-1/2
__device__ float g_scin  [NMAX];               // in_deg^-1/2
__device__ int   g_off   [NMAX + 1];           // CSR offsets (by dst)
__device__ int   g_cursor[NMAX];               // placement cursors
__device__ int   g_bsum  [1024];               // block sums for scan
__device__ int   g_csrc  [EMAX];               // CSR payload: src node per slot
__device__ __align__(16) __half g_w16[DOUT * DIN];  // W^T as fp16 [n][k], 64 KB

// ---------------------------------------------------------------- zero both degree arrays
__global__ void k_zero(int n) {
    int i = blockIdx.x * blockDim.x + threadIdx.x;
    if (i < n) { g_indeg[i] = 0; g_outdeg[i] = 0; }
}

// ---------------------------------------------------------------- dst histogram (8/thread)
__global__ void k_count_dst(const int* __restrict__ dst, int nE) {
    int i = blockIdx.x * blockDim.x + threadIdx.x;
    int base = i * 8;
    if (base + 7 < nE) {
        int4 d0 = *(const int4*)&dst[base];
        int4 d1 = *(const int4*)&dst[base + 4];
        atomicAdd(&g_indeg[d0.x], 1);
        atomicAdd(&g_indeg[d0.y], 1);
        atomicAdd(&g_indeg[d0.z], 1);
        atomicAdd(&g_indeg[d0.w], 1);
        atomicAdd(&g_indeg[d1.x], 1);
        atomicAdd(&g_indeg[d1.y], 1);
        atomicAdd(&g_indeg[d1.z], 1);
        atomicAdd(&g_indeg[d1.w], 1);
    } else {
        for (int e = base; e < nE; e++) atomicAdd(&g_indeg[dst[e]], 1);
    }
}

// ---------------------------------------------------------------- src histogram (8/thread)
__global__ void k_count_src(const int* __restrict__ src, int nE) {
    int i = blockIdx.x * blockDim.x + threadIdx.x;
    int base = i * 8;
    if (base + 7 < nE) {
        int4 s0 = *(const int4*)&src[base];
        int4 s1 = *(const int4*)&src[base + 4];
        atomicAdd(&g_outdeg[s0.x], 1);
        atomicAdd(&g_outdeg[s0.y], 1);
        atomicAdd(&g_outdeg[s0.z], 1);
        atomicAdd(&g_outdeg[s0.w], 1);
        atomicAdd(&g_outdeg[s1.x], 1);
        atomicAdd(&g_outdeg[s1.y], 1);
        atomicAdd(&g_outdeg[s1.z], 1);
        atomicAdd(&g_outdeg[s1.w], 1);
    } else {
        for (int e = base; e < nE; e++) atomicAdd(&g_outdeg[src[e]], 1);
    }
}

// ---------------------------------------------------------------- prep B (fp16)
__global__ void k_prepB(const float* __restrict__ w) {
    int i = blockIdx.x * blockDim.x + threadIdx.x;
    if (i >= DIN * DOUT) return;
    int n = i / DIN, k = i % DIN;
    g_w16[i] = __float2half_rn(w[(size_t)k * DOUT + n]);
}

// ---------------------------------------------------------------- scan stage 1
__global__ __launch_bounds__(256) void k_scan1(int n) {
    __shared__ int sh[256];
    int i = blockIdx.x * 256 + threadIdx.x;
    int v = (i < n) ? g_indeg[i] : 0;
    sh[threadIdx.x] = v;
    __syncthreads();
    #pragma unroll
    for (int off = 1; off < 256; off <<= 1) {
        int t = (threadIdx.x >= off) ? sh[threadIdx.x - off] : 0;
        __syncthreads();
        sh[threadIdx.x] += t;
        __syncthreads();
    }
    if (i < n) g_off[i] = sh[threadIdx.x] - v;
    if (threadIdx.x == 255) g_bsum[blockIdx.x] = sh[255];
}

// ---------------------------------------------------------------- scan stage 2
__global__ __launch_bounds__(1024) void k_scan2(int nb) {
    __shared__ int sh[1024];
    int t = threadIdx.x;
    int v = (t < nb) ? g_bsum[t] : 0;
    sh[t] = v;
    __syncthreads();
    #pragma unroll
    for (int off = 1; off < 1024; off <<= 1) {
        int x = (t >= off) ? sh[t - off] : 0;
        __syncthreads();
        sh[t] += x;
        __syncthreads();
    }
    if (t < nb) g_bsum[t] = sh[t] - v;
}

// ---------------------------------------------------------------- scan stage 3 (+ scin)
__global__ void k_scan3(int n, int nE) {
    int i = blockIdx.x * blockDim.x + threadIdx.x;
    if (i < n) {
        int o = g_off[i] + g_bsum[blockIdx.x];
        g_off[i] = o;
        g_cursor[i] = o;
        g_scin[i] = rsqrtf(fmaxf((float)g_indeg[i], 1.0f));
    }
    if (i == 0) g_off[n] = nE;
}

// ---------------------------------------------------------------- CSR build (4 edges/thread)
__global__ void k_build(const int* __restrict__ src, const int* __restrict__ dst, int nE) {
    int i = blockIdx.x * blockDim.x + threadIdx.x;
    int base = i * 4;
    if (base + 3 < nE) {
        int4 s = *(const int4*)&src[base];
        int4 d = *(const int4*)&dst[base];
        int p0 = atomicAdd(&g_cursor[d.x], 1);
        int p1 = atomicAdd(&g_cursor[d.y], 1);
        int p2 = atomicAdd(&g_cursor[d.z], 1);
        int p3 = atomicAdd(&g_cursor[d.w], 1);
        g_csrc[p0] = s.x;
        g_csrc[p1] = s.y;
        g_csrc[p2] = s.z;
        g_csrc[p3] = s.w;
    } else {
        for (int e = base; e < nE; e++) {
            int p = atomicAdd(&g_cursor[dst[e]], 1);
            g_csrc[p] = src[e];
        }
    }
}

// ---------------------------------------------------------------- scout
__global__ void k_scout(int n) {
    int i = blockIdx.x * blockDim.x + threadIdx.x;
    if (i < n) g_scout[i] = rsqrtf(fmaxf((float)g_outdeg[i], 1.0f));
}

// ---------------------------------------------------------------- GEMM (fp16 HMMA + ldmatrix + reg prefetch)
// h = scout * (feat @ W), fp16 out. B (full K) resident in smem. 2 CTAs/SM.
#define BK      64
#define PITCH_A 72
#define PITCH_B 264

__device__ __forceinline__ void mma16816(float* d, const uint32_t* a, const uint32_t* b) {
    asm volatile(
        "mma.sync.aligned.m16n8k16.row.col.f32.f16.f16.f32 "
        "{%0,%1,%2,%3}, {%4,%5,%6,%7}, {%8,%9}, {%0,%1,%2,%3};"
        : "+f"(d[0]), "+f"(d[1]), "+f"(d[2]), "+f"(d[3])
        : "r"(a[0]), "r"(a[1]), "r"(a[2]), "r"(a[3]), "r"(b[0]), "r"(b[1]));
}

#define LDSM_X4(r0, r1, r2, r3, addr)                                           \
    asm volatile("ldmatrix.sync.aligned.m8n8.x4.shared.b16 {%0,%1,%2,%3}, [%4];" \
                 : "=r"(r0), "=r"(r1), "=r"(r2), "=r"(r3) : "r"(addr))

#define GEMM_SMEM ((128 * PITCH_B + 128 * PITCH_A) * 2)  /* 86,016 B */

__global__ __launch_bounds__(256, 2) void k_gemm_mma(const float* __restrict__ feat, int M) {
    extern __shared__ __half sm[];
    __half* Bs = sm;                       // [128 n][PITCH_B] full K fp16
    __half* As = Bs + 128 * PITCH_B;       // [128 r][PITCH_A] one chunk

    const int tid  = threadIdx.x;
    const int wid  = tid >> 5, lane = tid & 31;
    const int g    = lane >> 2, t = lane & 3;
    const int wm   = wid & 3, wn = wid >> 2;     // warp grid 4(M) x 2(N)
    const int brow = blockIdx.x * 128;

    // ---- B resident copy
    #pragma unroll
    for (int i = 0; i < 16; i++) {
        int idx = tid + i * 256;
        int n   = idx >> 5;
        int j   = (idx & 31) * 8;
        *(uint4*)&Bs[n * PITCH_B + j] = *(const uint4*)&g_w16[n * DIN + j];
    }

    float acc[2][8][4];
    #pragma unroll
    for (int m = 0; m < 2; m++)
        #pragma unroll
        for (int s = 0; s < 8; s++)
            #pragma unroll
            for (int q = 0; q < 4; q++) acc[m][s][q] = 0.f;

    // ---- ldmatrix per-lane base addresses
    const int la = lane & 7;
    const int lb = (lane >> 3) & 1;
    const int lc = (lane >> 4) & 1;
    uint32_t a_base = (uint32_t)__cvta_generic_to_shared(As)
                    + (uint32_t)((wm * 32 + la + lb * 8) * PITCH_A) * 2 + (uint32_t)lc * 16;
    uint32_t b_base = (uint32_t)__cvta_generic_to_shared(Bs)
                    + (uint32_t)((wn * 64 + lc * 8 + la) * PITCH_B) * 2 + (uint32_t)lb * 16;

    // ---- prefetch chunk 0 into registers
    const int pr_r  = tid >> 4;             // per-thread A row (fixed)
    const int pr_c4 = (tid & 15) * 4;       // per-thread A col group (fixed)
    const int pr_gr = brow + pr_r;
    float4 v[8];
    #pragma unroll
    for (int i = 0; i < 8; i++) {
        int gr = pr_gr + (i * 256 >> 4);    // rows stride by 16 per i
        v[i] = (gr < M) ? *(const float4*)&feat[(size_t)gr * DIN + pr_c4]
                        : make_float4(0.f, 0.f, 0.f, 0.f);
    }

    __syncthreads();   // B ready

    for (int c = 0; c < 4; c++) {
        // ---- convert + store chunk c from registers
        #pragma unroll
        for (int i = 0; i < 8; i++) {
            int r = pr_r + i * 16;
            float4 x = v[i];
            __half2 h0 = __floats2half2_rn(x.x, x.y);
            __half2 h1 = __floats2half2_rn(x.z, x.w);
            *(uint2*)&As[r * PITCH_A + pr_c4] = make_uint2(*(uint32_t*)&h0, *(uint32_t*)&h1);
        }
        __syncthreads();

        // ---- prefetch chunk c+1 (overlaps MMA below)
        if (c < 3) {
            #pragma unroll
            for (int i = 0; i < 8; i++) {
                int gr = pr_gr + i * 16;
                v[i] = (gr < M) ? *(const float4*)&feat[(size_t)gr * DIN + (c + 1) * BK + pr_c4]
                                : make_float4(0.f, 0.f, 0.f, 0.f);
            }
        }

        // ---- MMA chunk c
        const int kb = c * BK;
        #pragma unroll
        for (int ks = 0; ks < 4; ks++) {
            const int kk = ks * 16;
            uint32_t a[2][4];
            #pragma unroll
            for (int m = 0; m < 2; m++) {
                uint32_t ad = a_base + (uint32_t)(m * 16 * PITCH_A) * 2 + (uint32_t)kk * 2;
                LDSM_X4(a[m][0], a[m][1], a[m][2], a[m][3], ad);
            }
            #pragma unroll
            for (int j = 0; j < 4; j++) {
                uint32_t q0, q1, q2, q3;
                uint32_t bd = b_base + (uint32_t)(j * 16 * PITCH_B) * 2 + (uint32_t)(kb + kk) * 2;
                LDSM_X4(q0, q1, q2, q3, bd);
                uint32_t b0[2] = {q0, q1};
                uint32_t b1[2] = {q2, q3};
                #pragma unroll
                for (int m = 0; m < 2; m++) {
                    mma16816(acc[m][2 * j],     a[m], b0);
                    mma16816(acc[m][2 * j + 1], a[m], b1);
                }
            }
        }
        __syncthreads();
    }

    // ---- epilogue: scale by scout[row], store fp16
    #pragma unroll
    for (int m = 0; m < 2; m++) {
        int r0 = brow + wm * 32 + m * 16 + g;
        int r1 = r0 + 8;
        float so0 = (r0 < M) ? __ldg(&g_scout[r0]) : 0.f;
        float so1 = (r1 < M) ? __ldg(&g_scout[r1]) : 0.f;
        #pragma unroll
        for (int s = 0; s < 8; s++) {
            int cb = wn * 64 + s * 8 + 2 * t;
            if (r0 < M) *(__half2*)&g_h16[(size_t)r0 * DOUT + cb] =
                __floats2half2_rn(acc[m][s][0] * so0, acc[m][s][1] * so0);
            if (r1 < M) *(__half2*)&g_h16[(size_t)r1 * DOUT + cb] =
                __floats2half2_rn(acc[m][s][2] * so1, acc[m][s][3] * so1);
        }
    }
}

// ---------------------------------------------------------------- gather-agg
// Full warp per dst node; lane owns 4 consecutive cols (uint2 of fp16).
// No intra-warp divergence. h already scout-scaled -> pure sum.
__global__ __launch_bounds__(256) void k_gather(float* __restrict__ out,
                                                const float* __restrict__ bias,
                                                int M) {
    long gid  = (long)blockIdx.x * blockDim.x + threadIdx.x;
    int  node = (int)(gid >> 5);
    int  lane = (int)(gid & 31);
    if (node >= M) return;

    int beg = g_off[node];
    int end = g_off[node + 1];

    const uint2* hp = (const uint2*)g_h16;   // row = 32 uint2 (128 halves)
    float acc[4];
    #pragma unroll
    for (int j = 0; j < 4; j++) acc[j] = 0.f;

    int e = beg;
    for (; e + 4 <= end; e += 4) {
        int s0 = __ldcs(&g_csrc[e]),   s1 = __ldcs(&g_csrc[e+1]);
        int s2 = __ldcs(&g_csrc[e+2]), s3 = __ldcs(&g_csrc[e+3]);
        uint2 q0 = __ldg(hp + (size_t)s0 * 32 + lane);
        uint2 q1 = __ldg(hp + (size_t)s1 * 32 + lane);
        uint2 q2 = __ldg(hp + (size_t)s2 * 32 + lane);
        uint2 q3 = __ldg(hp + (size_t)s3 * 32 + lane);
        #pragma unroll
        for (int p = 0; p < 2; p++) {
            uint32_t u0 = (&q0.x)[p], u1 = (&q1.x)[p], u2 = (&q2.x)[p], u3 = (&q3.x)[p];
            float2 f0 = __half22float2(*(__half2*)&u0);
            float2 f1 = __half22float2(*(__half2*)&u1);
            float2 f2 = __half22float2(*(__half2*)&u2);
            float2 f3 = __half22float2(*(__half2*)&u3);
            acc[2*p]   += (f0.x + f1.x) + (f2.x + f3.x);
            acc[2*p+1] += (f0.y + f1.y) + (f2.y + f3.y);
        }
    }
    for (; e < end; e++) {
        int s = __ldcs(&g_csrc[e]);
        uint2 q = __ldg(hp + (size_t)s * 32 + lane);
        #pragma unroll
        for (int p = 0; p < 2; p++) {
            uint32_t u = (&q.x)[p];
            float2 f = __half22float2(*(__half2*)&u);
            acc[2*p]   += f.x;
            acc[2*p+1] += f.y;
        }
    }

    float sc = g_scin[node];
    float4 b = *(const float4*)&bias[lane * 4];
    float4 r = make_float4(fmaf(acc[0], sc, b.x), fmaf(acc[1], sc, b.y),
                           fmaf(acc[2], sc, b.z), fmaf(acc[3], sc, b.w));
    __stcs((float4*)&out[(size_t)node * DOUT + lane * 4], r);
}

// ---------------------------------------------------------------- launch
extern "C" void kernel_launch(void* const* d_in, const int* in_sizes, int n_in,
                              void* d_out, int out_size) {
    const float* feat   = (const float*)d_in[0];
    const float* weight = (const float*)d_in[1];
    const float* bias   = (const float*)d_in[2];
    const int*   src    = (const int*)  d_in[3];
    const int*   dst    = (const int*)  d_in[4];

    int M  = in_sizes[0] / DIN;   // 100000
    int nE = in_sizes[3];         // 3200000
    int nb = (M + 255) / 256;
    int nE8 = (nE + 7) / 8;
    int nE4 = (nE + 3) / 4;

    static cudaStream_t s2;
    static cudaEvent_t evFork, evJoin;
    static int inited = 0;
    if (!inited) {
        cudaFuncSetAttribute(k_gemm_mma, cudaFuncAttributeMaxDynamicSharedMemorySize, GEMM_SMEM);
        cudaStreamCreateWithFlags(&s2, cudaStreamNonBlocking);
        cudaEventCreateWithFlags(&evFork, cudaEventDisableTiming);
        cudaEventCreateWithFlags(&evJoin, cudaEventDisableTiming);
        inited = 1;
    }

    // ---- shared prologue: zero both degree arrays, then fork (R13 structure)
    k_zero<<<(M + 255) / 256, 256>>>(M);
    cudaEventRecord(evFork, 0);
    cudaStreamWaitEvent(s2, evFork, 0);

    // ---- s2: src-scale + gemm branch (scout before gemm epilogue)
    k_count_src<<<(nE8 + 255) / 256, 256, 0, s2>>>(src, nE);
    k_scout    <<<(M + 255) / 256, 256, 0, s2>>>(M);
    k_prepB    <<<(DIN * DOUT + 255) / 256, 256, 0, s2>>>(weight);
    k_gemm_mma <<<(M + 127) / 128, 256, GEMM_SMEM, s2>>>(feat, M);
    cudaEventRecord(evJoin, s2);

    // ---- main: CSR branch
    k_count_dst<<<(nE8 + 255) / 256, 256>>>(dst, nE);
    k_scan1<<<nb, 256>>>(M);
    k_scan2<<<1, 1024>>>(nb);
    k_scan3<<<nb, 256>>>(M, nE);
    k_build<<<(nE4 + 255) / 256, 256>>>(src, dst, nE);

    // ---- join, then gather
    cudaStreamWaitEvent(0, evJoin, 0);
    long gather_threads = (long)M * 32;
    k_gather<<<(unsigned)((gather_threads + 255) / 256), 256>>>((float*)d_out, bias, M);
}